// round 14
// baseline (speedup 1.0000x reference)
#include <cuda_runtime.h>

#define CH 64
#define MAXN 65536
#define MAXDEG 64

// Scratch (no allocs allowed).
__device__ int   g_deg[MAXN];
__device__ int   g_bucket[(size_t)MAXN * MAXDEG];
__device__ float g_colsum[CH];
__device__ float g_sumsq[CH];
__device__ int   g_idx64;

#define FFMA2(acc, a, b) \
    asm("fma.rn.f32x2 %0, %1, %2, %0;" : "+l"(acc) : "l"(a), "l"(b))
#define PACK2(out, lo, hi) \
    asm("mov.b64 %0, {%1, %2};" : "=l"(out) : "f"(lo), "f"(hi))
#define UNPACK2(lo, hi, in) \
    asm("mov.b64 {%0, %1}, %2;" : "=f"(lo), "=f"(hi) : "l"(in))

// Dynamic smem layout for k_mlp (bytes):
//   [0, 17408)            sW0  64 x 68 floats
//   [17408, 34816)        sW1
//   [34816, 34816+65536)  hp   16 warps x 8 pairs x 64 ch x float2
//   [+65536, +66048)      bsum[64], bss[64]
#define SM_W1   17408
#define SM_HP   34816
#define SM_BSUM (34816 + 65536)
#define SM_TOTAL (SM_BSUM + 512)

// ---------------------------------------------------------------------------
// K1: zero degree counters + reduction buffers, detect index dtype.
// ---------------------------------------------------------------------------
__global__ void k_prep(const int* __restrict__ ei32, int N, int E) {
    int i = blockIdx.x * blockDim.x + threadIdx.x;
    if (i < N) g_deg[i] = 0;
    if (blockIdx.x == 0) {
        if (threadIdx.x < CH) { g_colsum[threadIdx.x] = 0.f; g_sumsq[threadIdx.x] = 0.f; }
        if (threadIdx.x == 0) {
            // int64 edge_index => high 32-bit word of every entry is 0.
            int allz = 1;
            int cnt = (E < 64) ? E : 64;
            for (int t = 0; t < cnt; t++) allz &= (ei32[2 * t + 1] == 0);
            g_idx64 = allz;
        }
    }
}

// ---------------------------------------------------------------------------
// K2: single-pass bucket scatter; slot = atomic return value.
// ---------------------------------------------------------------------------
__global__ void k_bucket(const void* __restrict__ ei, int E) {
    const int idx64 = g_idx64;
    const long long* e64 = (const long long*)ei;
    const int*       e32 = (const int*)ei;
    int i = blockIdx.x * blockDim.x + threadIdx.x;
    if (i < E) {
        int src, dst;
        if (idx64) { src = (int)e64[i]; dst = (int)e64[E + i]; }
        else       { src = e32[i];      dst = e32[E + i]; }
        int slot = atomicAdd(&g_deg[dst], 1);
        if (slot < MAXDEG)
            g_bucket[(size_t)dst * MAXDEG + slot] = src;
    }
}

// ---------------------------------------------------------------------------
// K3: dedicated gather — warp per row; the 205MB L2 stream runs at LTS
// throughput. agg written into `out` (k_mlp reads it back before overwriting).
// ---------------------------------------------------------------------------
__global__ void __launch_bounds__(256)
k_gather(const float* __restrict__ x, float* __restrict__ agg, int N) {
    const int lane = threadIdx.x & 31;
    const int row  = blockIdx.x * 8 + (threadIdx.x >> 5);
    if (row >= N) return;
    const float2* x2 = reinterpret_cast<const float2*>(x);
    int deg = g_deg[row];
    if (deg > MAXDEG) deg = MAXDEG;
    const int* nb = g_bucket + (size_t)row * MAXDEG;
    float2 acc0 = x2[row * 32 + lane];
    float2 acc1 = make_float2(0.f, 0.f);
    float2 acc2 = make_float2(0.f, 0.f);
    float2 acc3 = make_float2(0.f, 0.f);
    int j = 0;
    for (; j + 4 <= deg; j += 4) {
        int s0 = nb[j];
        int s1 = nb[j + 1];
        int s2 = nb[j + 2];
        int s3 = nb[j + 3];
        float2 v0 = x2[s0 * 32 + lane];
        float2 v1 = x2[s1 * 32 + lane];
        float2 v2 = x2[s2 * 32 + lane];
        float2 v3 = x2[s3 * 32 + lane];
        acc0.x += v0.x; acc0.y += v0.y;
        acc1.x += v1.x; acc1.y += v1.y;
        acc2.x += v2.x; acc2.y += v2.y;
        acc3.x += v3.x; acc3.y += v3.y;
    }
    for (; j < deg; j++) {
        int s0 = nb[j];
        float2 v0 = x2[s0 * 32 + lane];
        acc0.x += v0.x; acc0.y += v0.y;
    }
    acc0.x += acc1.x; acc0.y += acc1.y;
    acc2.x += acc3.x; acc2.y += acc3.y;
    acc0.x += acc2.x; acc0.y += acc2.y;
    reinterpret_cast<float2*>(agg)[row * 32 + lane] = acc0;
}

// ---------------------------------------------------------------------------
// Pair-packed 64x64 GEMM over 8 row-pairs; accumulators stay packed in pa.
// hp reads are uniform (broadcast); weight LDS.128 amortized over 16 rows.
// ---------------------------------------------------------------------------
__device__ __forceinline__ void gemm16(
    const float4* __restrict__ wa, const float4* __restrict__ wb,
    const float2 (*__restrict__ hp)[CH], unsigned long long pa[8][2]) {
    #pragma unroll
    for (int p = 0; p < 8; p++) { pa[p][0] = 0ull; pa[p][1] = 0ull; }
    #pragma unroll
    for (int kk = 0; kk < 16; kk++) {
        float4 va = wa[kk];
        float4 vb = wb[kk];
        unsigned long long wax, way, waz, waw, wbx, wby, wbz, wbw;
        PACK2(wax, va.x, va.x); PACK2(way, va.y, va.y);
        PACK2(waz, va.z, va.z); PACK2(waw, va.w, va.w);
        PACK2(wbx, vb.x, vb.x); PACK2(wby, vb.y, vb.y);
        PACK2(wbz, vb.z, vb.z); PACK2(wbw, vb.w, vb.w);
        #pragma unroll
        for (int p = 0; p < 8; p++) {
            const ulonglong2* hq = reinterpret_cast<const ulonglong2*>(hp[p]);
            ulonglong2 q0 = hq[2 * kk];          // channels 4kk, 4kk+1 (paired)
            ulonglong2 q1 = hq[2 * kk + 1];      // channels 4kk+2, 4kk+3
            FFMA2(pa[p][0], q0.x, wax); FFMA2(pa[p][0], q0.y, way);
            FFMA2(pa[p][0], q1.x, waz); FFMA2(pa[p][0], q1.y, waw);
            FFMA2(pa[p][1], q0.x, wbx); FFMA2(pa[p][1], q0.y, wby);
            FFMA2(pa[p][1], q1.x, wbz); FFMA2(pa[p][1], q1.y, wbw);
        }
    }
}

__device__ __forceinline__ float warp_sum(float v) {
    #pragma unroll
    for (int o = 16; o; o >>= 1) v += __shfl_xor_sync(0xffffffffu, v, o);
    return v;
}

// ---------------------------------------------------------------------------
// K4: MLP only. 512 threads = 16 warps sharing ONE weight copy; warp = 16
// rows (8 pairs). LN unpacks accumulators lazily per pair (low reg peak).
// launch_bounds(512,2): 2 CTAs/SM -> 32 warps/SM; regs capped at 64.
// ---------------------------------------------------------------------------
__global__ void __launch_bounds__(512, 2)
k_mlp(const float* __restrict__ W0, const float* __restrict__ ln0w,
      const float* __restrict__ ln0b, const float* __restrict__ W1,
      const float* __restrict__ ln1w, const float* __restrict__ ln1b,
      float* __restrict__ out, int N) {
    extern __shared__ __align__(16) char dsm[];
    float (*sW0)[68] = reinterpret_cast<float (*)[68]>(dsm);
    float (*sW1)[68] = reinterpret_cast<float (*)[68]>(dsm + SM_W1);
    float* bsum = reinterpret_cast<float*>(dsm + SM_BSUM);
    float* bss  = bsum + CH;

    const int tid  = threadIdx.x;
    const int lane = tid & 31;
    const int warp = tid >> 5;

    float2 (*hp)[CH] = reinterpret_cast<float2 (*)[CH]>(
        dsm + SM_HP + warp * 8 * CH * sizeof(float2));

    for (int i = tid; i < CH * CH; i += blockDim.x) {
        sW0[i >> 6][i & 63] = W0[i];
        sW1[i >> 6][i & 63] = W1[i];
    }
    if (tid < CH) { bsum[tid] = 0.f; bss[tid] = 0.f; }
    #pragma unroll
    for (int p = 0; p < 8; p++) {
        hp[p][lane]      = make_float2(0.f, 0.f);
        hp[p][lane + 32] = make_float2(0.f, 0.f);
    }

    const float w0a = ln0w[lane], w0b = ln0w[lane + 32];
    const float b0a = ln0b[lane], b0b = ln0b[lane + 32];
    const float w1a = ln1w[lane], w1b = ln1w[lane + 32];
    const float b1a = ln1b[lane], b1b = ln1b[lane + 32];
    __syncthreads();

    const float4* wa0 = reinterpret_cast<const float4*>(&sW0[lane][0]);
    const float4* wb0 = reinterpret_cast<const float4*>(&sW0[lane + 32][0]);
    const float4* wa1 = reinterpret_cast<const float4*>(&sW1[lane][0]);
    const float4* wb1 = reinterpret_cast<const float4*>(&sW1[lane + 32][0]);
    const float2* o2  = reinterpret_cast<const float2*>(out);

    float cs0 = 0.f, cs1 = 0.f, ss0 = 0.f, ss1 = 0.f;

    const int base = (blockIdx.x * 16 + warp) * 16;

    // ---- load 16 agg rows (coalesced), stage pair-packed ----
    #pragma unroll
    for (int r = 0; r < 16; r++) {
        int row = base + r;
        if (row < N) {
            float2 h = o2[row * 32 + lane];
            float* hpf = reinterpret_cast<float*>(&hp[r >> 1][0]);
            int half = r & 1;
            hpf[4 * lane + half]     = h.x;   // channel 2*lane
            hpf[4 * lane + 2 + half] = h.y;   // channel 2*lane+1
        }
    }
    __syncwarp();

    unsigned long long pa[8][2];

    // ---- layer 0 GEMM ----
    gemm16(wa0, wb0, hp, pa);
    __syncwarp();

    // ---- LayerNorm 0 + ReLU, per pair (lazy unpack), restage ----
    #pragma unroll
    for (int p = 0; p < 8; p++) {
        float e0, o0, e1, o1;
        UNPACK2(e0, o0, pa[p][0]);   // ch group a: (row even, row odd)
        UNPACK2(e1, o1, pa[p][1]);   // ch group b
        float se = warp_sum(e0 + e1);
        float so = warp_sum(o0 + o1);
        float mue = se * (1.f / 64.f), muo = so * (1.f / 64.f);
        float de0 = e0 - mue, de1 = e1 - mue;
        float do0 = o0 - muo, do1 = o1 - muo;
        float qe = warp_sum(de0 * de0 + de1 * de1);
        float qo = warp_sum(do0 * do0 + do1 * do1);
        float inve = rsqrtf(qe * (1.f / 64.f) + 1e-5f);
        float invo = rsqrtf(qo * (1.f / 64.f) + 1e-5f);
        float* hpf = reinterpret_cast<float*>(&hp[p][0]);
        hpf[2 * lane]              = fmaxf(fmaf(de0 * inve, w0a, b0a), 0.f);
        hpf[2 * (lane + 32)]       = fmaxf(fmaf(de1 * inve, w0b, b0b), 0.f);
        hpf[2 * lane + 1]          = fmaxf(fmaf(do0 * invo, w0a, b0a), 0.f);
        hpf[2 * (lane + 32) + 1]   = fmaxf(fmaf(do1 * invo, w0b, b0b), 0.f);
    }
    __syncwarp();

    // ---- layer 1 GEMM ----
    gemm16(wa1, wb1, hp, pa);

    // ---- LayerNorm 1 + ReLU + store + GraphNorm partials ----
    #pragma unroll
    for (int p = 0; p < 8; p++) {
        float e0, o0, e1, o1;
        UNPACK2(e0, o0, pa[p][0]);
        UNPACK2(e1, o1, pa[p][1]);
        float se = warp_sum(e0 + e1);
        float so = warp_sum(o0 + o1);
        float mue = se * (1.f / 64.f), muo = so * (1.f / 64.f);
        float de0 = e0 - mue, de1 = e1 - mue;
        float do0 = o0 - muo, do1 = o1 - muo;
        float qe = warp_sum(de0 * de0 + de1 * de1);
        float qo = warp_sum(do0 * do0 + do1 * do1);
        float inve = rsqrtf(qe * (1.f / 64.f) + 1e-5f);
        float invo = rsqrtf(qo * (1.f / 64.f) + 1e-5f);
        int rowe = base + 2 * p;
        int rowo = rowe + 1;
        if (rowe < N) {
            float v0 = fmaxf(fmaf(de0 * inve, w1a, b1a), 0.f);
            float v1 = fmaxf(fmaf(de1 * inve, w1b, b1b), 0.f);
            float* orow = out + (size_t)rowe * CH;
            orow[lane] = v0; orow[lane + 32] = v1;
            cs0 += v0; cs1 += v1;
            ss0 = fmaf(v0, v0, ss0); ss1 = fmaf(v1, v1, ss1);
        }
        if (rowo < N) {
            float v0 = fmaxf(fmaf(do0 * invo, w1a, b1a), 0.f);
            float v1 = fmaxf(fmaf(do1 * invo, w1b, b1b), 0.f);
            float* orow = out + (size_t)rowo * CH;
            orow[lane] = v0; orow[lane + 32] = v1;
            cs0 += v0; cs1 += v1;
            ss0 = fmaf(v0, v0, ss0); ss1 = fmaf(v1, v1, ss1);
        }
    }
    __syncwarp();

    // column sum / sumsq partials: register -> shared -> 128 global atomics.
    atomicAdd(&bsum[lane], cs0);
    atomicAdd(&bsum[lane + 32], cs1);
    atomicAdd(&bss[lane], ss0);
    atomicAdd(&bss[lane + 32], ss1);
    __syncthreads();
    if (tid < CH) {
        atomicAdd(&g_colsum[tid], bsum[tid]);
        atomicAdd(&g_sumsq[tid],  bss[tid]);
    }
}

// ---------------------------------------------------------------------------
// K5: final GraphNorm, in-place, float4. var = E[h^2] - 2*am*mu + am^2.
// ---------------------------------------------------------------------------
__global__ void k_final(const float* __restrict__ gnw, const float* __restrict__ gnb,
                        const float* __restrict__ gna, float* __restrict__ out,
                        int N) {
    const float invN = 1.f / (float)N;
    const int t = blockIdx.x * blockDim.x + threadIdx.x;
    const int c0 = (t & 15) * 4;
    float am[4], w[4], b[4];
    #pragma unroll
    for (int j = 0; j < 4; j++) {
        int c = c0 + j;
        float mu  = g_colsum[c] * invN;
        float a   = gna[c] * mu;
        float ex2 = g_sumsq[c] * invN;
        float var = ex2 - 2.f * a * mu + a * a;
        am[j] = a;
        w[j]  = gnw[c] * rsqrtf(var + 1e-5f);
        b[j]  = gnb[c];
    }
    float4* o4 = reinterpret_cast<float4*>(out);
    const int total = N * 16;
    for (int i = t; i < total; i += gridDim.x * blockDim.x) {
        float4 h = o4[i];
        h.x = fmaf(h.x - am[0], w[0], b[0]);
        h.y = fmaf(h.y - am[1], w[1], b[1]);
        h.z = fmaf(h.z - am[2], w[2], b[2]);
        h.w = fmaf(h.w - am[3], w[3], b[3]);
        o4[i] = h;
    }
}

// ---------------------------------------------------------------------------
extern "C" void kernel_launch(void* const* d_in, const int* in_sizes, int n_in,
                              void* d_out, int out_size) {
    const float* x    = (const float*)d_in[0];
    const void*  ei   = d_in[1];
    const float* W0   = (const float*)d_in[2];
    const float* ln0w = (const float*)d_in[3];
    const float* ln0b = (const float*)d_in[4];
    const float* W1   = (const float*)d_in[5];
    const float* ln1w = (const float*)d_in[6];
    const float* ln1b = (const float*)d_in[7];
    const float* gnw  = (const float*)d_in[8];
    const float* gnb  = (const float*)d_in[9];
    const float* gna  = (const float*)d_in[10];

    const int N = in_sizes[0] / CH;
    const int E = in_sizes[1] / 2;
    float* out = (float*)d_out;

    // Host-side attribute set (not a stream op; safe during graph capture).
    cudaFuncSetAttribute(k_mlp, cudaFuncAttributeMaxDynamicSharedMemorySize,
                         SM_TOTAL);

    k_prep<<<(N + 255) / 256, 256>>>((const int*)ei, N, E);   // launch 1
    k_bucket<<<(E + 255) / 256, 256>>>(ei, E);                // launch 2
    k_gather<<<(N + 7) / 8, 256>>>(x, out, N);                // launch 3

    const int rows_per_block = 16 * 16;                       // 16 warps x 16
    const int mlp_blocks = (N + rows_per_block - 1) / rows_per_block;
    k_mlp<<<mlp_blocks, 512, SM_TOTAL>>>(W0, ln0w, ln0b,      // launch 4 (profiled)
                                         W1, ln1w, ln1b, out, N);

    k_final<<<2048, 256>>>(gnw, gnb, gna, out, N);            // launch 5
}

// round 15
// speedup vs baseline: 1.2022x; 1.2022x over previous
#include <cuda_runtime.h>

#define CH 64
#define MAXN 65536
#define MAXDEG 64

// Scratch (no allocs allowed).
__device__ int   g_deg[MAXN];
__device__ int   g_bucket[(size_t)MAXN * MAXDEG];
__device__ float g_colsum[CH];
__device__ float g_sumsq[CH];
__device__ int   g_idx64;

// ---- dynamic smem layout for k_mlp (bytes) ----
#define PW 68                      // padded row pitch (floats): bank = 4g+t, conflict-free
#define SZW (64 * PW * 4)          // 17408 per weight array
#define SM_W0HI 0
#define SM_W0LO (SZW)
#define SM_W1HI (2 * SZW)
#define SM_W1LO (3 * SZW)
#define SM_H    (4 * SZW)                      // 8 warps x 16 rows x PW floats
#define SM_LNP  (SM_H + 8 * 16 * PW * 4)       // ln0w|ln0b|ln1w|ln1b (4 x 64 f32)
#define SM_BSUM (SM_LNP + 1024)                // bsum[64], bss[64]
#define SM_TOTAL (SM_BSUM + 512)

// ---------------------------------------------------------------------------
// K1: zero degree counters + reduction buffers, detect index dtype.
// ---------------------------------------------------------------------------
__global__ void k_prep(const int* __restrict__ ei32, int N, int E) {
    int i = blockIdx.x * blockDim.x + threadIdx.x;
    if (i < N) g_deg[i] = 0;
    if (blockIdx.x == 0) {
        if (threadIdx.x < CH) { g_colsum[threadIdx.x] = 0.f; g_sumsq[threadIdx.x] = 0.f; }
        if (threadIdx.x == 0) {
            // int64 edge_index => high 32-bit word of every entry is 0.
            int allz = 1;
            int cnt = (E < 64) ? E : 64;
            for (int t = 0; t < cnt; t++) allz &= (ei32[2 * t + 1] == 0);
            g_idx64 = allz;
        }
    }
}

// ---------------------------------------------------------------------------
// K2: single-pass bucket scatter; slot = atomic return value.
// ---------------------------------------------------------------------------
__global__ void k_bucket(const void* __restrict__ ei, int E) {
    const int idx64 = g_idx64;
    const long long* e64 = (const long long*)ei;
    const int*       e32 = (const int*)ei;
    int i = blockIdx.x * blockDim.x + threadIdx.x;
    if (i < E) {
        int src, dst;
        if (idx64) { src = (int)e64[i]; dst = (int)e64[E + i]; }
        else       { src = e32[i];      dst = e32[E + i]; }
        int slot = atomicAdd(&g_deg[dst], 1);
        if (slot < MAXDEG)
            g_bucket[(size_t)dst * MAXDEG + slot] = src;
    }
}

// ---------------------------------------------------------------------------
// K3: dedicated gather — warp per row; the 205MB L2 stream runs at LTS
// throughput. agg written into `out` (k_mlp reads it back before overwriting).
// ---------------------------------------------------------------------------
__global__ void __launch_bounds__(256)
k_gather(const float* __restrict__ x, float* __restrict__ agg, int N) {
    const int lane = threadIdx.x & 31;
    const int row  = blockIdx.x * 8 + (threadIdx.x >> 5);
    if (row >= N) return;
    const float2* x2 = reinterpret_cast<const float2*>(x);
    int deg = g_deg[row];
    if (deg > MAXDEG) deg = MAXDEG;
    const int* nb = g_bucket + (size_t)row * MAXDEG;
    float2 acc0 = x2[row * 32 + lane];
    float2 acc1 = make_float2(0.f, 0.f);
    float2 acc2 = make_float2(0.f, 0.f);
    float2 acc3 = make_float2(0.f, 0.f);
    int j = 0;
    for (; j + 4 <= deg; j += 4) {
        int s0 = nb[j];
        int s1 = nb[j + 1];
        int s2 = nb[j + 2];
        int s3 = nb[j + 3];
        float2 v0 = x2[s0 * 32 + lane];
        float2 v1 = x2[s1 * 32 + lane];
        float2 v2 = x2[s2 * 32 + lane];
        float2 v3 = x2[s3 * 32 + lane];
        acc0.x += v0.x; acc0.y += v0.y;
        acc1.x += v1.x; acc1.y += v1.y;
        acc2.x += v2.x; acc2.y += v2.y;
        acc3.x += v3.x; acc3.y += v3.y;
    }
    for (; j < deg; j++) {
        int s0 = nb[j];
        float2 v0 = x2[s0 * 32 + lane];
        acc0.x += v0.x; acc0.y += v0.y;
    }
    acc0.x += acc1.x; acc0.y += acc1.y;
    acc2.x += acc3.x; acc2.y += acc3.y;
    acc0.x += acc2.x; acc0.y += acc2.y;
    reinterpret_cast<float2*>(agg)[row * 32 + lane] = acc0;
}

// ---------------------------------------------------------------------------
// tf32 helpers
// ---------------------------------------------------------------------------
__device__ __forceinline__ unsigned f2tf(float x) {
    unsigned r;
    asm("cvt.rna.tf32.f32 %0, %1;" : "=r"(r) : "f"(x));
    return r;
}
__device__ __forceinline__ void tf32_split(float x, unsigned& hi, unsigned& lo) {
    asm("cvt.rna.tf32.f32 %0, %1;" : "=r"(hi) : "f"(x));
    float r = x - __uint_as_float(hi);
    asm("cvt.rna.tf32.f32 %0, %1;" : "=r"(lo) : "f"(r));
}
__device__ __forceinline__ void mma8(float d[4], unsigned a0, unsigned a1,
                                     unsigned a2, unsigned a3,
                                     unsigned b0, unsigned b1) {
    asm("mma.sync.aligned.m16n8k8.row.col.f32.tf32.tf32.f32 "
        "{%0,%1,%2,%3}, {%4,%5,%6,%7}, {%8,%9}, {%0,%1,%2,%3};"
        : "+f"(d[0]), "+f"(d[1]), "+f"(d[2]), "+f"(d[3])
        : "r"(a0), "r"(a1), "r"(a2), "r"(a3), "r"(b0), "r"(b1));
}

// One 16x64x64 layer with 3xTF32: D = h @ W^T. hw: [16][PW] row-major smem.
// whi/wlo: [64][PW] smem (pre-split). Lane = (g = lane>>2, t = lane&3).
__device__ __forceinline__ void mma_layer(
    const float* __restrict__ hw, const float* __restrict__ whi,
    const float* __restrict__ wlo, int g, int t, float D[8][4]) {
    #pragma unroll
    for (int n = 0; n < 8; n++) { D[n][0] = D[n][1] = D[n][2] = D[n][3] = 0.f; }
    #pragma unroll
    for (int ks = 0; ks < 8; ks++) {
        const int k0 = ks * 8 + t;
        unsigned ah0, al0, ah1, al1, ah2, al2, ah3, al3;
        tf32_split(hw[g * PW + k0],           ah0, al0);
        tf32_split(hw[(g + 8) * PW + k0],     ah1, al1);
        tf32_split(hw[g * PW + k0 + 4],       ah2, al2);
        tf32_split(hw[(g + 8) * PW + k0 + 4], ah3, al3);
        #pragma unroll
        for (int n = 0; n < 8; n++) {
            const int col = 8 * n + g;
            unsigned bh0 = __float_as_uint(whi[col * PW + k0]);
            unsigned bh1 = __float_as_uint(whi[col * PW + k0 + 4]);
            unsigned bl0 = __float_as_uint(wlo[col * PW + k0]);
            unsigned bl1 = __float_as_uint(wlo[col * PW + k0 + 4]);
            mma8(D[n], ah0, ah1, ah2, ah3, bh0, bh1);
            mma8(D[n], ah0, ah1, ah2, ah3, bl0, bl1);
            mma8(D[n], al0, al1, al2, al3, bh0, bh1);
        }
    }
}

// LayerNorm + ReLU on mma-layout D, writing normalized rows into hw smem.
// Row g in D[n][0..1], row g+8 in D[n][2..3]; cols = 8n + 2t (+1).
__device__ __forceinline__ void ln_stage(
    float D[8][4], const float* __restrict__ lw, const float* __restrict__ lb,
    int g, int t, float* __restrict__ hw) {
    float s0 = 0.f, s1 = 0.f;
    #pragma unroll
    for (int n = 0; n < 8; n++) { s0 += D[n][0] + D[n][1]; s1 += D[n][2] + D[n][3]; }
    s0 += __shfl_xor_sync(0xffffffffu, s0, 1);
    s0 += __shfl_xor_sync(0xffffffffu, s0, 2);
    s1 += __shfl_xor_sync(0xffffffffu, s1, 1);
    s1 += __shfl_xor_sync(0xffffffffu, s1, 2);
    float mu0 = s0 * (1.f / 64.f), mu1 = s1 * (1.f / 64.f);
    float q0 = 0.f, q1 = 0.f;
    #pragma unroll
    for (int n = 0; n < 8; n++) {
        float d0 = D[n][0] - mu0, d1 = D[n][1] - mu0;
        float d2 = D[n][2] - mu1, d3 = D[n][3] - mu1;
        q0 += d0 * d0 + d1 * d1;
        q1 += d2 * d2 + d3 * d3;
    }
    q0 += __shfl_xor_sync(0xffffffffu, q0, 1);
    q0 += __shfl_xor_sync(0xffffffffu, q0, 2);
    q1 += __shfl_xor_sync(0xffffffffu, q1, 1);
    q1 += __shfl_xor_sync(0xffffffffu, q1, 2);
    float inv0 = rsqrtf(q0 * (1.f / 64.f) + 1e-5f);
    float inv1 = rsqrtf(q1 * (1.f / 64.f) + 1e-5f);
    #pragma unroll
    for (int n = 0; n < 8; n++) {
        int c = 8 * n + 2 * t;
        float2 w2 = *reinterpret_cast<const float2*>(&lw[c]);
        float2 b2 = *reinterpret_cast<const float2*>(&lb[c]);
        float2 r0, r1;
        r0.x = fmaxf(fmaf((D[n][0] - mu0) * inv0, w2.x, b2.x), 0.f);
        r0.y = fmaxf(fmaf((D[n][1] - mu0) * inv0, w2.y, b2.y), 0.f);
        r1.x = fmaxf(fmaf((D[n][2] - mu1) * inv1, w2.x, b2.x), 0.f);
        r1.y = fmaxf(fmaf((D[n][3] - mu1) * inv1, w2.y, b2.y), 0.f);
        *reinterpret_cast<float2*>(&hw[g * PW + c])       = r0;
        *reinterpret_cast<float2*>(&hw[(g + 8) * PW + c]) = r1;
    }
}

// ---------------------------------------------------------------------------
// K4: MLP via tensor cores (mma.sync tf32, 3xTF32). Warp = 16 rows.
// 8 warps/block share one pre-split weight copy. Dynamic smem ~104KB,
// 2 CTAs/SM. GraphNorm partials fused in epilogue.
// ---------------------------------------------------------------------------
__global__ void __launch_bounds__(256, 2)
k_mlp(const float* __restrict__ W0, const float* __restrict__ ln0w,
      const float* __restrict__ ln0b, const float* __restrict__ W1,
      const float* __restrict__ ln1w, const float* __restrict__ ln1b,
      float* __restrict__ out, int N) {
    extern __shared__ __align__(16) char dsm[];
    float* w0hi = reinterpret_cast<float*>(dsm + SM_W0HI);
    float* w0lo = reinterpret_cast<float*>(dsm + SM_W0LO);
    float* w1hi = reinterpret_cast<float*>(dsm + SM_W1HI);
    float* w1lo = reinterpret_cast<float*>(dsm + SM_W1LO);
    float* lnp  = reinterpret_cast<float*>(dsm + SM_LNP);
    float* bsum = reinterpret_cast<float*>(dsm + SM_BSUM);
    float* bss  = bsum + CH;

    const int tid  = threadIdx.x;
    const int lane = tid & 31;
    const int warp = tid >> 5;
    const int g    = lane >> 2;
    const int t    = lane & 3;

    float* hw = reinterpret_cast<float*>(dsm + SM_H) + warp * 16 * PW;

    // ---- pre-split weights into tf32 hi/lo (once per block) ----
    for (int i = tid; i < CH * CH; i += blockDim.x) {
        int r = i >> 6, c = i & 63;
        float w = W0[i];
        unsigned hb = f2tf(w);
        float hf = __uint_as_float(hb);
        w0hi[r * PW + c] = hf;
        w0lo[r * PW + c] = __uint_as_float(f2tf(w - hf));
        float v = W1[i];
        unsigned hb1 = f2tf(v);
        float hf1 = __uint_as_float(hb1);
        w1hi[r * PW + c] = hf1;
        w1lo[r * PW + c] = __uint_as_float(f2tf(v - hf1));
    }
    if (tid < CH) {
        lnp[tid]       = ln0w[tid];
        lnp[64 + tid]  = ln0b[tid];
        lnp[128 + tid] = ln1w[tid];
        lnp[192 + tid] = ln1b[tid];
        bsum[tid] = 0.f;
        bss[tid]  = 0.f;
    }
    __syncthreads();

    const int base = (blockIdx.x * 8 + warp) * 16;
    const float2* o2 = reinterpret_cast<const float2*>(out);

    // ---- stage 16 agg rows (coalesced) into row-major smem ----
    #pragma unroll
    for (int r = 0; r < 16; r++) {
        int row = base + r;
        float2 v = (row < N) ? o2[row * 32 + lane] : make_float2(0.f, 0.f);
        *reinterpret_cast<float2*>(&hw[r * PW + 2 * lane]) = v;
    }
    __syncwarp();

    float D[8][4];

    // ---- layer 0: GEMM (tensor) -> LN -> ReLU back into hw ----
    mma_layer(hw, w0hi, w0lo, g, t, D);
    __syncwarp();
    ln_stage(D, lnp, lnp + 64, g, t, hw);
    __syncwarp();

    // ---- layer 1 ----
    mma_layer(hw, w1hi, w1lo, g, t, D);
    __syncwarp();
    ln_stage(D, lnp + 128, lnp + 192, g, t, hw);
    __syncwarp();

    // ---- epilogue: coalesced store + GraphNorm partials ----
    float cs0 = 0.f, cs1 = 0.f, ss0 = 0.f, ss1 = 0.f;
    #pragma unroll
    for (int r = 0; r < 16; r++) {
        int row = base + r;
        if (row < N) {
            float2 v = *reinterpret_cast<const float2*>(&hw[r * PW + 2 * lane]);
            reinterpret_cast<float2*>(out)[row * 32 + lane] = v;
            cs0 += v.x; cs1 += v.y;
            ss0 = fmaf(v.x, v.x, ss0);
            ss1 = fmaf(v.y, v.y, ss1);
        }
    }
    atomicAdd(&bsum[2 * lane], cs0);
    atomicAdd(&bsum[2 * lane + 1], cs1);
    atomicAdd(&bss[2 * lane], ss0);
    atomicAdd(&bss[2 * lane + 1], ss1);
    __syncthreads();
    if (tid < CH) {
        atomicAdd(&g_colsum[tid], bsum[tid]);
        atomicAdd(&g_sumsq[tid],  bss[tid]);
    }
}

// ---------------------------------------------------------------------------
// K5: final GraphNorm, in-place, float4. var = E[h^2] - 2*am*mu + am^2.
// ---------------------------------------------------------------------------
__global__ void k_final(const float* __restrict__ gnw, const float* __restrict__ gnb,
                        const float* __restrict__ gna, float* __restrict__ out,
                        int N) {
    const float invN = 1.f / (float)N;
    const int t = blockIdx.x * blockDim.x + threadIdx.x;
    const int c0 = (t & 15) * 4;
    float am[4], w[4], b[4];
    #pragma unroll
    for (int j = 0; j < 4; j++) {
        int c = c0 + j;
        float mu  = g_colsum[c] * invN;
        float a   = gna[c] * mu;
        float ex2 = g_sumsq[c] * invN;
        float var = ex2 - 2.f * a * mu + a * a;
        am[j] = a;
        w[j]  = gnw[c] * rsqrtf(var + 1e-5f);
        b[j]  = gnb[c];
    }
    float4* o4 = reinterpret_cast<float4*>(out);
    const int total = N * 16;
    for (int i = t; i < total; i += gridDim.x * blockDim.x) {
        float4 h = o4[i];
        h.x = fmaf(h.x - am[0], w[0], b[0]);
        h.y = fmaf(h.y - am[1], w[1], b[1]);
        h.z = fmaf(h.z - am[2], w[2], b[2]);
        h.w = fmaf(h.w - am[3], w[3], b[3]);
        o4[i] = h;
    }
}

// ---------------------------------------------------------------------------
extern "C" void kernel_launch(void* const* d_in, const int* in_sizes, int n_in,
                              void* d_out, int out_size) {
    const float* x    = (const float*)d_in[0];
    const void*  ei   = d_in[1];
    const float* W0   = (const float*)d_in[2];
    const float* ln0w = (const float*)d_in[3];
    const float* ln0b = (const float*)d_in[4];
    const float* W1   = (const float*)d_in[5];
    const float* ln1w = (const float*)d_in[6];
    const float* ln1b = (const float*)d_in[7];
    const float* gnw  = (const float*)d_in[8];
    const float* gnb  = (const float*)d_in[9];
    const float* gna  = (const float*)d_in[10];

    const int N = in_sizes[0] / CH;
    const int E = in_sizes[1] / 2;
    float* out = (float*)d_out;

    // Host-side attribute set (not a stream op; safe during graph capture).
    cudaFuncSetAttribute(k_mlp, cudaFuncAttributeMaxDynamicSharedMemorySize,
                         SM_TOTAL);

    k_prep<<<(N + 255) / 256, 256>>>((const int*)ei, N, E);   // launch 1
    k_bucket<<<(E + 255) / 256, 256>>>(ei, E);                // launch 2
    k_gather<<<(N + 7) / 8, 256>>>(x, out, N);                // launch 3

    const int rows_per_block = 8 * 16;                        // 8 warps x 16
    const int mlp_blocks = (N + rows_per_block - 1) / rows_per_block;
    k_mlp<<<mlp_blocks, 256, SM_TOTAL>>>(W0, ln0w, ln0b,      // launch 4 (profiled)
                                         W1, ln1w, ln1b, out, N);

    k_final<<<2048, 256>>>(gnw, gnb, gna, out, N);            // launch 5
}